// round 2
// baseline (speedup 1.0000x reference)
#include <cuda_runtime.h>
#include <math.h>

// Problem constants
#define BN   32
#define CC   3072
#define KK   11
#define HW   784
#define NCLS 200
#define NCH  12           // c-chunks for k_ab
#define CCH  (CC / NCH)   // 256 channels per chunk
#define GRP  8            // batches per L2 group
#define NGRP (BN / GRP)

typedef unsigned long long ull;

// Scratch (device globals; no allocation allowed)
__device__ float g_ab_part[NCH * BN * KK * HW];   // 13.2 MB partial ab
__device__ float g_asq[KK];
__device__ float g_g[BN * CC];                    // sum_k feat_mod

// ---------------------------------------------------------------------------
// f32x2 helpers (sm_100+ packed fp32 FMA; ptxas never auto-fuses these)
// ---------------------------------------------------------------------------
__device__ __forceinline__ void ffma2(ull& d, ull a, ull b) {
    asm("fma.rn.f32x2 %0, %1, %2, %0;" : "+l"(d) : "l"(a), "l"(b));
}
__device__ __forceinline__ ull pack2(float lo, float hi) {
    ull r; asm("mov.b64 %0, {%1, %2};" : "=l"(r) : "f"(lo), "f"(hi)); return r;
}
__device__ __forceinline__ float2 unpack2(ull v) {
    float2 r; asm("mov.b64 {%0, %1}, %2;" : "=f"(r.x), "=f"(r.y) : "l"(v)); return r;
}

// ---------------------------------------------------------------------------
// Kernel 0: a_sq[k] = sum_c w_land[k,c]^2
// ---------------------------------------------------------------------------
__global__ void k_asq(const float* __restrict__ wl) {
    int k = blockIdx.x;
    int tid = threadIdx.x;
    float s = 0.f;
    for (int c = tid; c < CC; c += 128) {
        float w = wl[k * CC + c];
        s += w * w;
    }
    __shared__ float red[128];
    red[tid] = s;
    __syncthreads();
    for (int o = 64; o; o >>= 1) {
        if (tid < o) red[tid] += red[tid + o];
        __syncthreads();
    }
    if (tid == 0) g_asq[k] = red[0];
}

// ---------------------------------------------------------------------------
// Kernel 1: partial ab over a 256-channel chunk, half the pixels per block.
// grid (NCH, GRP, 2), block 196. Thread owns one float2 pixel pair (f32x2).
// ---------------------------------------------------------------------------
__global__ void __launch_bounds__(196) k_ab(const float* __restrict__ x,
                                            const float* __restrict__ wl,
                                            int b0) {
    __shared__ ull ws2[KK * CCH];          // {w,w} duplicated pairs, 22.5 KB
    const int ch = blockIdx.x;
    const int b  = b0 + blockIdx.y;
    const int ph = blockIdx.z;             // pixel half 0/1
    const int c0 = ch * CCH;
    const int tid = threadIdx.x;

    for (int i = tid; i < KK * CCH; i += 196) {
        int k = i / CCH, c = i - k * CCH;
        float w = wl[k * CC + c0 + c];
        ws2[i] = pack2(w, w);
    }
    __syncthreads();

    ull acc[KK];
#pragma unroll
    for (int k = 0; k < KK; ++k) acc[k] = 0ull;

    // thread's float2 pixel index within a row
    const ull* xp = reinterpret_cast<const ull*>(x + ((size_t)b * CC + c0) * HW)
                    + ph * 196 + tid;

#pragma unroll 4
    for (int c = 0; c < CCH; ++c) {
        ull xv = xp[(size_t)c * (HW / 2)];
#pragma unroll
        for (int k = 0; k < KK; ++k) {
            ull w2 = ws2[k * CCH + c];     // broadcast LDS.64
            ffma2(acc[k], xv, w2);
        }
    }

    ull* gp = reinterpret_cast<ull*>(g_ab_part);
    size_t base = ((size_t)(ch * BN + b) * KK) * HW;
    int po = ph * 196 + tid;
#pragma unroll
    for (int k = 0; k < KK; ++k)
        gp[(base + (size_t)k * HW) / 2 + po] = acc[k];
}

// ---------------------------------------------------------------------------
// Kernel 2: combine chunks, softmax over K (b_sq cancels), write maps.
// grid (GRP, 4 pixel slices), block 196 (1 pixel per thread)
// ---------------------------------------------------------------------------
__global__ void k_softmax(float* __restrict__ maps, int b0) {
    const int b = b0 + blockIdx.x;
    const int p = blockIdx.y * 196 + threadIdx.x;

    __shared__ float asq[KK];
    if (threadIdx.x < KK) asq[threadIdx.x] = g_asq[threadIdx.x];
    __syncthreads();

    float s[KK];
#pragma unroll
    for (int k = 0; k < KK; ++k) s[k] = 0.f;

    for (int ch = 0; ch < NCH; ++ch) {
        size_t base = ((size_t)(ch * BN + b) * KK) * HW + p;
#pragma unroll
        for (int k = 0; k < KK; ++k)
            s[k] += g_ab_part[base + (size_t)k * HW];
    }
    float mx = -1e30f;
#pragma unroll
    for (int k = 0; k < KK; ++k) {
        s[k] = 2.f * s[k] - asq[k];
        mx = fmaxf(mx, s[k]);
    }
    float sum = 0.f;
#pragma unroll
    for (int k = 0; k < KK; ++k) {
        s[k] = __expf(s[k] - mx);
        sum += s[k];
    }
    float inv = 1.f / sum;
#pragma unroll
    for (int k = 0; k < KK; ++k)
        maps[((size_t)(b * KK + k)) * HW + p] = s[k] * inv;
}

// ---------------------------------------------------------------------------
// Kernel 3: feat[b,c,k] = (1/784) * sum_p maps[b,k,p] * x[b,c,p] * mod,
// plus g[b,c] = sum_k feat_mod. x comes from L2 (same group as k_ab).
// grid (48, GRP), block 512 (16 warps x 4 channels). f32x2 FMAs; lane owns
// a float4 pixel group -> conflict-free LDS.128 on maps, coalesced LDG.128.
// ---------------------------------------------------------------------------
__global__ void __launch_bounds__(512, 1) k_feat(const float* __restrict__ x,
                                                 const float* __restrict__ maps,
                                                 const float* __restrict__ mod,
                                                 float* __restrict__ feat,
                                                 int b0) {
    __shared__ float4 maps_s[KK * 196];    // 34.5 KB
    const int b   = b0 + blockIdx.y;
    const int tid = threadIdx.x;

    const float4* mg = reinterpret_cast<const float4*>(maps + (size_t)b * KK * HW);
    for (int i = tid; i < KK * 196; i += 512) maps_s[i] = mg[i];
    __syncthreads();

    const int warp = tid >> 5, lane = tid & 31;
    const int c0 = blockIdx.x * 64 + warp * 4;
    const float4* xb = reinterpret_cast<const float4*>(x + ((size_t)b * CC + c0) * HW);

    ull acc[4][KK][2];
#pragma unroll
    for (int j = 0; j < 4; ++j)
#pragma unroll
        for (int k = 0; k < KK; ++k) { acc[j][k][0] = 0ull; acc[j][k][1] = 0ull; }

    for (int p4 = lane; p4 < 196; p4 += 32) {
        float4 xv0 = xb[p4];
        float4 xv1 = xb[196 + p4];
        float4 xv2 = xb[392 + p4];
        float4 xv3 = xb[588 + p4];
        ull xl0 = pack2(xv0.x, xv0.y), xh0 = pack2(xv0.z, xv0.w);
        ull xl1 = pack2(xv1.x, xv1.y), xh1 = pack2(xv1.z, xv1.w);
        ull xl2 = pack2(xv2.x, xv2.y), xh2 = pack2(xv2.z, xv2.w);
        ull xl3 = pack2(xv3.x, xv3.y), xh3 = pack2(xv3.z, xv3.w);
#pragma unroll
        for (int k = 0; k < KK; ++k) {
            float4 mv = maps_s[k * 196 + p4];
            ull ml = pack2(mv.x, mv.y), mh = pack2(mv.z, mv.w);
            ffma2(acc[0][k][0], xl0, ml); ffma2(acc[0][k][1], xh0, mh);
            ffma2(acc[1][k][0], xl1, ml); ffma2(acc[1][k][1], xh1, mh);
            ffma2(acc[2][k][0], xl2, ml); ffma2(acc[2][k][1], xh2, mh);
            ffma2(acc[3][k][0], xl3, ml); ffma2(acc[3][k][1], xh3, mh);
        }
    }

    const float inv_hw = 1.f / (float)HW;
    float gs0 = 0.f, gs1 = 0.f, gs2 = 0.f, gs3 = 0.f;
#pragma unroll
    for (int j = 0; j < 4; ++j) {
#pragma unroll
        for (int k = 0; k < KK; ++k) {
            float2 a = unpack2(acc[j][k][0]);
            float2 c2 = unpack2(acc[j][k][1]);
            float s = (a.x + a.y) + (c2.x + c2.y);
#pragma unroll
            for (int o = 16; o; o >>= 1)
                s += __shfl_down_sync(0xffffffffu, s, o);
            if (lane == 0) {
                float v = s * inv_hw * mod[(c0 + j) * KK + k];
                feat[((size_t)b * CC + c0 + j) * KK + k] = v;
                if (j == 0) gs0 += v; else if (j == 1) gs1 += v;
                else if (j == 2) gs2 += v; else gs3 += v;
            }
        }
    }
    if (lane == 0) {
        g_g[b * CC + c0 + 0] = gs0;
        g_g[b * CC + c0 + 1] = gs1;
        g_g[b * CC + c0 + 2] = gs2;
        g_g[b * CC + c0 + 3] = gs3;
    }
}

// ---------------------------------------------------------------------------
// Kernel 4: attn[b,k] = sum_p maps[b,k,p].  grid (BN, KK), block 256
// ---------------------------------------------------------------------------
__global__ void k_attn(const float* __restrict__ maps, float* __restrict__ attn) {
    const int b = blockIdx.x, k = blockIdx.y, tid = threadIdx.x;
    float s = 0.f;
    const float* mp = maps + ((size_t)b * KK + k) * HW;
    for (int i = tid; i < HW; i += 256) s += mp[i];
    __shared__ float red[256];
    red[tid] = s;
    __syncthreads();
    for (int o = 128; o; o >>= 1) {
        if (tid < o) red[tid] += red[tid + o];
        __syncthreads();
    }
    if (tid == 0) attn[b * KK + k] = red[0];
}

// ---------------------------------------------------------------------------
// Kernel 5: scores[b,n] = sum_c g[b,c] * w_cls[n,c]; 4 batches per block.
// grid (NCLS, BN/4), block 128
// ---------------------------------------------------------------------------
__global__ void k_scores(const float* __restrict__ wcls,
                         float* __restrict__ scores) {
    const int n = blockIdx.x;
    const int b0 = blockIdx.y * 4;
    const int tid = threadIdx.x;
    float s0 = 0.f, s1 = 0.f, s2 = 0.f, s3 = 0.f;
    const float* wn = wcls + (size_t)n * CC;
    for (int c = tid; c < CC; c += 128) {
        float w = wn[c];
        s0 = fmaf(w, g_g[(b0 + 0) * CC + c], s0);
        s1 = fmaf(w, g_g[(b0 + 1) * CC + c], s1);
        s2 = fmaf(w, g_g[(b0 + 2) * CC + c], s2);
        s3 = fmaf(w, g_g[(b0 + 3) * CC + c], s3);
    }
    __shared__ float red[4][128];
    red[0][tid] = s0; red[1][tid] = s1; red[2][tid] = s2; red[3][tid] = s3;
    __syncthreads();
    for (int o = 64; o; o >>= 1) {
        if (tid < o) {
            red[0][tid] += red[0][tid + o];
            red[1][tid] += red[1][tid + o];
            red[2][tid] += red[2][tid + o];
            red[3][tid] += red[3][tid + o];
        }
        __syncthreads();
    }
    if (tid == 0) {
#pragma unroll
        for (int j = 0; j < 4; ++j)
            scores[(b0 + j) * NCLS + n] = red[j][0];
    }
}

// ---------------------------------------------------------------------------
extern "C" void kernel_launch(void* const* d_in, const int* in_sizes, int n_in,
                              void* d_out, int out_size) {
    const float* x    = (const float*)d_in[0];
    const float* wl   = (const float*)d_in[1];
    const float* mod  = (const float*)d_in[2];
    const float* wcls = (const float*)d_in[3];

    float* out    = (float*)d_out;
    float* feat   = out;                                   // (B,C,K)
    float* scores = out + (size_t)BN * CC * KK;            // (B,NC)
    float* maps   = scores + (size_t)BN * NCLS;            // (B,K,HW)
    float* attn   = maps + (size_t)BN * KK * HW;           // (B,K)

    k_asq<<<KK, 128>>>(wl);
    for (int g = 0; g < NGRP; ++g) {
        int b0 = g * GRP;
        k_ab<<<dim3(NCH, GRP, 2), 196>>>(x, wl, b0);
        k_softmax<<<dim3(GRP, 4), 196>>>(maps, b0);
        k_feat<<<dim3(CC / 64, GRP), 512>>>(x, maps, mod, feat, b0);
    }
    k_attn<<<dim3(BN, KK), 256>>>(maps, attn);
    k_scores<<<dim3(NCLS, BN / 4), 128>>>(wcls, scores);
}

// round 3
// speedup vs baseline: 3.0084x; 3.0084x over previous
#include <cuda_runtime.h>
#include <math.h>

// Problem constants
#define BN   32
#define CC   3072
#define KK   11
#define HW   784
#define NCLS 200
#define NCH  12           // c-chunks for k_ab
#define CCH  (CC / NCH)   // 256 channels per chunk

typedef unsigned long long ull;

// Scratch (device globals; no allocation allowed)
__device__ float g_ab_part[NCH * BN * KK * HW];   // 13.2 MB partial ab
__device__ float g_asq[KK];
__device__ float g_g[BN * CC];                    // sum_k feat_mod

// ---------------------------------------------------------------------------
// f32x2 helpers (sm_100+ packed fp32 FMA; ptxas never auto-fuses these)
// ---------------------------------------------------------------------------
__device__ __forceinline__ void ffma2(ull& d, ull a, ull b) {
    asm("fma.rn.f32x2 %0, %1, %2, %0;" : "+l"(d) : "l"(a), "l"(b));
}
__device__ __forceinline__ ull pack2(float lo, float hi) {
    ull r; asm("mov.b64 %0, {%1, %2};" : "=l"(r) : "f"(lo), "f"(hi)); return r;
}
__device__ __forceinline__ float2 unpack2(ull v) {
    float2 r; asm("mov.b64 {%0, %1}, %2;" : "=f"(r.x), "=f"(r.y) : "l"(v)); return r;
}

// ---------------------------------------------------------------------------
// Kernel 0: a_sq[k] = sum_c w_land[k,c]^2
// ---------------------------------------------------------------------------
__global__ void k_asq(const float* __restrict__ wl) {
    int k = blockIdx.x;
    int tid = threadIdx.x;
    float s = 0.f;
    for (int c = tid; c < CC; c += 128) {
        float w = wl[k * CC + c];
        s += w * w;
    }
    __shared__ float red[128];
    red[tid] = s;
    __syncthreads();
    for (int o = 64; o; o >>= 1) {
        if (tid < o) red[tid] += red[tid + o];
        __syncthreads();
    }
    if (tid == 0) g_asq[k] = red[0];
}

// ---------------------------------------------------------------------------
// Kernel 1: partial ab over a 256-channel chunk, half the pixels per block.
// grid (NCH, BN, 2), block 196. Thread owns one float2 pixel pair (f32x2).
// acc = 11 ull = 22 regs -> high occupancy; DRAM-bound by design.
// ---------------------------------------------------------------------------
__global__ void __launch_bounds__(196) k_ab(const float* __restrict__ x,
                                            const float* __restrict__ wl) {
    __shared__ ull ws2[KK * CCH];          // {w,w} duplicated pairs, 22.5 KB
    const int ch = blockIdx.x;
    const int b  = blockIdx.y;
    const int ph = blockIdx.z;             // pixel half 0/1
    const int c0 = ch * CCH;
    const int tid = threadIdx.x;

    for (int i = tid; i < KK * CCH; i += 196) {
        int k = i >> 8, c = i & (CCH - 1);
        float w = wl[k * CC + c0 + c];
        ws2[i] = pack2(w, w);
    }
    __syncthreads();

    ull acc[KK];
#pragma unroll
    for (int k = 0; k < KK; ++k) acc[k] = 0ull;

    const ull* xp = reinterpret_cast<const ull*>(x + ((size_t)b * CC + c0) * HW)
                    + ph * 196 + tid;

#pragma unroll 4
    for (int c = 0; c < CCH; ++c) {
        ull xv = xp[(size_t)c * (HW / 2)];
#pragma unroll
        for (int k = 0; k < KK; ++k)
            ffma2(acc[k], xv, ws2[k * CCH + c]);   // broadcast LDS.64
    }

    ull* gp = reinterpret_cast<ull*>(g_ab_part);
    size_t base = ((size_t)(ch * BN + b) * KK) * HW;
    int po = ph * 196 + tid;
#pragma unroll
    for (int k = 0; k < KK; ++k)
        gp[(base + (size_t)k * HW) / 2 + po] = acc[k];
}

// ---------------------------------------------------------------------------
// Kernel 2: combine chunks, softmax over K (b_sq cancels), write maps.
// grid (BN, 4 pixel slices), block 196 (1 pixel per thread)
// ---------------------------------------------------------------------------
__global__ void k_softmax(float* __restrict__ maps) {
    const int b = blockIdx.x;
    const int p = blockIdx.y * 196 + threadIdx.x;

    __shared__ float asq[KK];
    if (threadIdx.x < KK) asq[threadIdx.x] = g_asq[threadIdx.x];
    __syncthreads();

    float s[KK];
#pragma unroll
    for (int k = 0; k < KK; ++k) s[k] = 0.f;

#pragma unroll
    for (int ch = 0; ch < NCH; ++ch) {
        size_t base = ((size_t)(ch * BN + b) * KK) * HW + p;
#pragma unroll
        for (int k = 0; k < KK; ++k)
            s[k] += g_ab_part[base + (size_t)k * HW];
    }
    float mx = -1e30f;
#pragma unroll
    for (int k = 0; k < KK; ++k) {
        s[k] = 2.f * s[k] - asq[k];
        mx = fmaxf(mx, s[k]);
    }
    float sum = 0.f;
#pragma unroll
    for (int k = 0; k < KK; ++k) {
        s[k] = __expf(s[k] - mx);
        sum += s[k];
    }
    float inv = 1.f / sum;
#pragma unroll
    for (int k = 0; k < KK; ++k)
        maps[((size_t)(b * KK + k)) * HW + p] = s[k] * inv;
}

// ---------------------------------------------------------------------------
// Kernel 3: feat[b,c,k] = (1/784) * sum_p maps[b,k,p] * x[b,c,p] * mod,
// plus g[b,c] = sum_k feat_mod.
// grid (96, 32), block 256 (8 warps x 4 channels). Lane owns float2 pixel
// pairs -> acc[4][11] ull = 88 regs (fits 128-reg cap, no spill).
// ---------------------------------------------------------------------------
__global__ void __launch_bounds__(256, 2) k_feat(const float* __restrict__ x,
                                                 const float* __restrict__ maps,
                                                 const float* __restrict__ mod,
                                                 float* __restrict__ feat) {
    __shared__ ull maps_s[KK * 392];       // 34.5 KB, [k][p2] float2 pairs
    const int b   = blockIdx.y;
    const int tid = threadIdx.x;

    const ull* mg = reinterpret_cast<const ull*>(maps + (size_t)b * KK * HW);
    for (int i = tid; i < KK * 392; i += 256) maps_s[i] = mg[i];
    __syncthreads();

    const int warp = tid >> 5, lane = tid & 31;
    const int c0 = blockIdx.x * 32 + warp * 4;
    const ull* xb = reinterpret_cast<const ull*>(x + ((size_t)b * CC + c0) * HW);

    ull acc[4][KK];
#pragma unroll
    for (int j = 0; j < 4; ++j)
#pragma unroll
        for (int k = 0; k < KK; ++k) acc[j][k] = 0ull;

    for (int p2 = lane; p2 < 392; p2 += 32) {
        ull x0 = xb[p2];
        ull x1 = xb[392 + p2];
        ull x2 = xb[784 + p2];
        ull x3 = xb[1176 + p2];
#pragma unroll
        for (int k = 0; k < KK; ++k) {
            ull m = maps_s[k * 392 + p2];  // conflict-free LDS.64
            ffma2(acc[0][k], x0, m);
            ffma2(acc[1][k], x1, m);
            ffma2(acc[2][k], x2, m);
            ffma2(acc[3][k], x3, m);
        }
    }

    const float inv_hw = 1.f / (float)HW;
#pragma unroll
    for (int j = 0; j < 4; ++j) {
        float gs = 0.f;
#pragma unroll
        for (int k = 0; k < KK; ++k) {
            float2 v = unpack2(acc[j][k]);
            float s = v.x + v.y;
#pragma unroll
            for (int o = 16; o; o >>= 1)
                s += __shfl_down_sync(0xffffffffu, s, o);
            if (lane == 0) {
                float r = s * inv_hw * mod[(c0 + j) * KK + k];
                feat[((size_t)b * CC + c0 + j) * KK + k] = r;
                gs += r;
            }
        }
        if (lane == 0) g_g[b * CC + c0 + j] = gs;
    }
}

// ---------------------------------------------------------------------------
// Kernel 4: attn[b,k] = sum_p maps[b,k,p].  grid (BN, KK), block 256
// ---------------------------------------------------------------------------
__global__ void k_attn(const float* __restrict__ maps, float* __restrict__ attn) {
    const int b = blockIdx.x, k = blockIdx.y, tid = threadIdx.x;
    float s = 0.f;
    const float* mp = maps + ((size_t)b * KK + k) * HW;
    for (int i = tid; i < HW; i += 256) s += mp[i];
    __shared__ float red[256];
    red[tid] = s;
    __syncthreads();
    for (int o = 128; o; o >>= 1) {
        if (tid < o) red[tid] += red[tid + o];
        __syncthreads();
    }
    if (tid == 0) attn[b * KK + k] = red[0];
}

// ---------------------------------------------------------------------------
// Kernel 5: scores[b,n] = sum_c g[b,c] * w_cls[n,c]; 4 batches per block.
// grid (NCLS, BN/4), block 128
// ---------------------------------------------------------------------------
__global__ void k_scores(const float* __restrict__ wcls,
                         float* __restrict__ scores) {
    const int n = blockIdx.x;
    const int b0 = blockIdx.y * 4;
    const int tid = threadIdx.x;
    float s0 = 0.f, s1 = 0.f, s2 = 0.f, s3 = 0.f;
    const float* wn = wcls + (size_t)n * CC;
    for (int c = tid; c < CC; c += 128) {
        float w = wn[c];
        s0 = fmaf(w, g_g[(b0 + 0) * CC + c], s0);
        s1 = fmaf(w, g_g[(b0 + 1) * CC + c], s1);
        s2 = fmaf(w, g_g[(b0 + 2) * CC + c], s2);
        s3 = fmaf(w, g_g[(b0 + 3) * CC + c], s3);
    }
    __shared__ float red[4][128];
    red[0][tid] = s0; red[1][tid] = s1; red[2][tid] = s2; red[3][tid] = s3;
    __syncthreads();
    for (int o = 64; o; o >>= 1) {
        if (tid < o) {
            red[0][tid] += red[0][tid + o];
            red[1][tid] += red[1][tid + o];
            red[2][tid] += red[2][tid + o];
            red[3][tid] += red[3][tid + o];
        }
        __syncthreads();
    }
    if (tid == 0) {
#pragma unroll
        for (int j = 0; j < 4; ++j)
            scores[(b0 + j) * NCLS + n] = red[j][0];
    }
}

// ---------------------------------------------------------------------------
extern "C" void kernel_launch(void* const* d_in, const int* in_sizes, int n_in,
                              void* d_out, int out_size) {
    const float* x    = (const float*)d_in[0];
    const float* wl   = (const float*)d_in[1];
    const float* mod  = (const float*)d_in[2];
    const float* wcls = (const float*)d_in[3];

    float* out    = (float*)d_out;
    float* feat   = out;                                   // (B,C,K)
    float* scores = out + (size_t)BN * CC * KK;            // (B,NC)
    float* maps   = scores + (size_t)BN * NCLS;            // (B,K,HW)
    float* attn   = maps + (size_t)BN * KK * HW;           // (B,K)

    k_asq<<<KK, 128>>>(wl);
    k_ab<<<dim3(NCH, BN, 2), 196>>>(x, wl);
    k_softmax<<<dim3(BN, 4), 196>>>(maps);
    k_feat<<<dim3(CC / 32, BN), 256>>>(x, maps, mod, feat);
    k_attn<<<dim3(BN, KK), 256>>>(maps, attn);
    k_scores<<<dim3(NCLS, BN / 4), 128>>>(wcls, scores);
}

// round 6
// speedup vs baseline: 3.4933x; 1.1612x over previous
#include <cuda_runtime.h>
#include <math.h>

// Problem constants
#define BN   32
#define CC   3072
#define KK   11
#define HW   784
#define NCLS 200
#define NCH  12           // c-chunks for k_ab
#define CCH  (CC / NCH)   // 256 channels per chunk

typedef unsigned long long ull;

// Scratch (device globals; no allocation allowed)
__device__ float g_ab_part[NCH * BN * KK * HW];   // 13.2 MB partial ab
__device__ float g_asq[KK];
__device__ float g_g[BN * CC];                    // sum_k feat_mod

// ---------------------------------------------------------------------------
// f32x2 helpers (sm_100+ packed fp32 FMA)
// ---------------------------------------------------------------------------
__device__ __forceinline__ void ffma2(ull& d, ull a, ull b) {
    asm("fma.rn.f32x2 %0, %1, %2, %0;" : "+l"(d) : "l"(a), "l"(b));
}
__device__ __forceinline__ ull pack2(float lo, float hi) {
    ull r; asm("mov.b64 %0, {%1, %2};" : "=l"(r) : "f"(lo), "f"(hi)); return r;
}
__device__ __forceinline__ float2 unpack2(ull v) {
    float2 r; asm("mov.b64 {%0, %1}, %2;" : "=f"(r.x), "=f"(r.y) : "l"(v)); return r;
}

// ---------------------------------------------------------------------------
// Kernel 0: a_sq[k] = sum_c w_land[k,c]^2
// ---------------------------------------------------------------------------
__global__ void k_asq(const float* __restrict__ wl) {
    int k = blockIdx.x;
    int tid = threadIdx.x;
    float s = 0.f;
    for (int c = tid; c < CC; c += 128) {
        float w = wl[k * CC + c];
        s += w * w;
    }
    __shared__ float red[128];
    red[tid] = s;
    __syncthreads();
    for (int o = 64; o; o >>= 1) {
        if (tid < o) red[tid] += red[tid + o];
        __syncthreads();
    }
    if (tid == 0) g_asq[k] = red[0];
}

// ---------------------------------------------------------------------------
// Kernel 1: partial ab over a 256-channel chunk, half the pixels per block.
// grid (NCH, BN, 2), block 196. Thread owns one float2 pixel pair.
// 4 channel-loads front-batched per iteration -> MLP 4 per thread.
// ---------------------------------------------------------------------------
__global__ void __launch_bounds__(196) k_ab(const float* __restrict__ x,
                                            const float* __restrict__ wl) {
    __shared__ ull ws2[KK * CCH];          // {w,w} duplicated pairs, 22.5 KB
    const int ch = blockIdx.x;
    const int b  = blockIdx.y;
    const int ph = blockIdx.z;             // pixel half 0/1
    const int c0 = ch * CCH;
    const int tid = threadIdx.x;

    for (int i = tid; i < KK * CCH; i += 196) {
        int k = i >> 8, c = i & (CCH - 1);
        float w = wl[k * CC + c0 + c];
        ws2[i] = pack2(w, w);
    }
    __syncthreads();

    ull acc[KK];
#pragma unroll
    for (int k = 0; k < KK; ++k) acc[k] = 0ull;

    const ull* xp = reinterpret_cast<const ull*>(x + ((size_t)b * CC + c0) * HW)
                    + ph * 196 + tid;

#pragma unroll 1
    for (int c = 0; c < CCH; c += 4) {
        // front-batched loads: 4 outstanding LDG.64 before any consumer
        ull a0 = xp[(size_t)(c + 0) * 392];
        ull a1 = xp[(size_t)(c + 1) * 392];
        ull a2 = xp[(size_t)(c + 2) * 392];
        ull a3 = xp[(size_t)(c + 3) * 392];
#pragma unroll
        for (int k = 0; k < KK; ++k) {
            ffma2(acc[k], a0, ws2[k * CCH + c + 0]);
            ffma2(acc[k], a1, ws2[k * CCH + c + 1]);
            ffma2(acc[k], a2, ws2[k * CCH + c + 2]);
            ffma2(acc[k], a3, ws2[k * CCH + c + 3]);
        }
    }

    ull* gp = reinterpret_cast<ull*>(g_ab_part);
    size_t base = ((size_t)(ch * BN + b) * KK) * HW;
    int po = ph * 196 + tid;
#pragma unroll
    for (int k = 0; k < KK; ++k)
        gp[(base + (size_t)k * HW) / 2 + po] = acc[k];
}

// ---------------------------------------------------------------------------
// Kernel 2: combine chunks, softmax over K (b_sq cancels), write maps.
// grid (BN, 4 pixel slices), block 196 (1 pixel per thread)
// ---------------------------------------------------------------------------
__global__ void k_softmax(float* __restrict__ maps) {
    const int b = blockIdx.x;
    const int p = blockIdx.y * 196 + threadIdx.x;

    __shared__ float asq[KK];
    if (threadIdx.x < KK) asq[threadIdx.x] = g_asq[threadIdx.x];
    __syncthreads();

    float s[KK];
#pragma unroll
    for (int k = 0; k < KK; ++k) s[k] = 0.f;

#pragma unroll
    for (int ch = 0; ch < NCH; ++ch) {
        size_t base = ((size_t)(ch * BN + b) * KK) * HW + p;
#pragma unroll
        for (int k = 0; k < KK; ++k)
            s[k] += g_ab_part[base + (size_t)k * HW];
    }
    float mx = -1e30f;
#pragma unroll
    for (int k = 0; k < KK; ++k) {
        s[k] = 2.f * s[k] - asq[k];
        mx = fmaxf(mx, s[k]);
    }
    float sum = 0.f;
#pragma unroll
    for (int k = 0; k < KK; ++k) {
        s[k] = __expf(s[k] - mx);
        sum += s[k];
    }
    float inv = 1.f / sum;
#pragma unroll
    for (int k = 0; k < KK; ++k)
        maps[((size_t)(b * KK + k)) * HW + p] = s[k] * inv;
}

// ---------------------------------------------------------------------------
// Kernel 3: feat[b,c,k] = (1/784) * sum_p maps[b,k,p] * x[b,c,p] * mod,
// plus g[b,c] = sum_k feat_mod.
// grid (96, 32), block 256 (8 warps x 4 channels). Software-pipelined pixel
// loop: next iteration's 4 LDG.64 issued before current FMAs -> MLP 8/warp.
// Batch order REVERSED vs k_ab so first waves hit x still in L2.
// ---------------------------------------------------------------------------
__global__ void __launch_bounds__(256, 2) k_feat(const float* __restrict__ x,
                                                 const float* __restrict__ maps,
                                                 const float* __restrict__ mod,
                                                 float* __restrict__ feat) {
    __shared__ ull maps_s[KK * 392 + 32];  // padded; pad zeroed
    const int b   = (BN - 1) - blockIdx.y;
    const int tid = threadIdx.x;

    const ull* mg = reinterpret_cast<const ull*>(maps + (size_t)b * KK * HW);
    for (int i = tid; i < KK * 392; i += 256) maps_s[i] = mg[i];
    if (tid < 32) maps_s[KK * 392 + tid] = 0ull;
    __syncthreads();

    const int warp = tid >> 5, lane = tid & 31;
    const int c0 = blockIdx.x * 32 + warp * 4;
    const ull* xb = reinterpret_cast<const ull*>(x + ((size_t)b * CC + c0) * HW);

    ull acc[4][KK];
#pragma unroll
    for (int j = 0; j < 4; ++j)
#pragma unroll
        for (int k = 0; k < KK; ++k) acc[j][k] = 0ull;

    // prologue: load pixel-pair group for p2 = lane (always valid)
    ull x0 = xb[lane];
    ull x1 = xb[392 + lane];
    ull x2 = xb[784 + lane];
    ull x3 = xb[1176 + lane];
    int p2 = lane;

#pragma unroll 1
    for (int i = 0; i < 13; ++i) {
        // prefetch next group (zero-fill past the end)
        int p2n = p2 + 32;
        ull n0 = 0ull, n1 = 0ull, n2 = 0ull, n3 = 0ull;
        if (p2n < 392) {
            n0 = xb[p2n];
            n1 = xb[392 + p2n];
            n2 = xb[784 + p2n];
            n3 = xb[1176 + p2n];
        }
        // consume current group (x==0 on tail; maps pad zeroed -> exact 0 adds)
#pragma unroll
        for (int k = 0; k < KK; ++k) {
            ull m = maps_s[k * 392 + p2];  // conflict-free LDS.64
            ffma2(acc[0][k], x0, m);
            ffma2(acc[1][k], x1, m);
            ffma2(acc[2][k], x2, m);
            ffma2(acc[3][k], x3, m);
        }
        x0 = n0; x1 = n1; x2 = n2; x3 = n3;
        p2 = p2n;
    }

    const float inv_hw = 1.f / (float)HW;
#pragma unroll
    for (int j = 0; j < 4; ++j) {
        float gs = 0.f;
#pragma unroll
        for (int k = 0; k < KK; ++k) {
            float2 v = unpack2(acc[j][k]);
            float s = v.x + v.y;
#pragma unroll
            for (int o = 16; o; o >>= 1)
                s += __shfl_down_sync(0xffffffffu, s, o);
            if (lane == 0) {
                float r = s * inv_hw * mod[(c0 + j) * KK + k];
                feat[((size_t)b * CC + c0 + j) * KK + k] = r;
                gs += r;
            }
        }
        if (lane == 0) g_g[b * CC + c0 + j] = gs;
    }
}

// ---------------------------------------------------------------------------
// Kernel 4: attn[b,k] = sum_p maps[b,k,p].  grid (BN, KK), block 256
// ---------------------------------------------------------------------------
__global__ void k_attn(const float* __restrict__ maps, float* __restrict__ attn) {
    const int b = blockIdx.x, k = blockIdx.y, tid = threadIdx.x;
    float s = 0.f;
    const float* mp = maps + ((size_t)b * KK + k) * HW;
    for (int i = tid; i < HW; i += 256) s += mp[i];
    __shared__ float red[256];
    red[tid] = s;
    __syncthreads();
    for (int o = 128; o; o >>= 1) {
        if (tid < o) red[tid] += red[tid + o];
        __syncthreads();
    }
    if (tid == 0) attn[b * KK + k] = red[0];
}

// ---------------------------------------------------------------------------
// Kernel 5: scores[b,n] = sum_c g[b,c] * w_cls[n,c]; 4 batches per block.
// grid (NCLS, BN/4), block 128
// ---------------------------------------------------------------------------
__global__ void k_scores(const float* __restrict__ wcls,
                         float* __restrict__ scores) {
    const int n = blockIdx.x;
    const int b0 = blockIdx.y * 4;
    const int tid = threadIdx.x;
    float s0 = 0.f, s1 = 0.f, s2 = 0.f, s3 = 0.f;
    const float* wn = wcls + (size_t)n * CC;
    for (int c = tid; c < CC; c += 128) {
        float w = wn[c];
        s0 = fmaf(w, g_g[(b0 + 0) * CC + c], s0);
        s1 = fmaf(w, g_g[(b0 + 1) * CC + c], s1);
        s2 = fmaf(w, g_g[(b0 + 2) * CC + c], s2);
        s3 = fmaf(w, g_g[(b0 + 3) * CC + c], s3);
    }
    __shared__ float red[4][128];
    red[0][tid] = s0; red[1][tid] = s1; red[2][tid] = s2; red[3][tid] = s3;
    __syncthreads();
    for (int o = 64; o; o >>= 1) {
        if (tid < o) {
            red[0][tid] += red[0][tid + o];
            red[1][tid] += red[1][tid + o];
            red[2][tid] += red[2][tid + o];
            red[3][tid] += red[3][tid + o];
        }
        __syncthreads();
    }
    if (tid == 0) {
#pragma unroll
        for (int j = 0; j < 4; ++j)
            scores[(b0 + j) * NCLS + n] = red[j][0];
    }
}

// ---------------------------------------------------------------------------
extern "C" void kernel_launch(void* const* d_in, const int* in_sizes, int n_in,
                              void* d_out, int out_size) {
    const float* x    = (const float*)d_in[0];
    const float* wl   = (const float*)d_in[1];
    const float* mod  = (const float*)d_in[2];
    const float* wcls = (const float*)d_in[3];

    float* out    = (float*)d_out;
    float* feat   = out;                                   // (B,C,K)
    float* scores = out + (size_t)BN * CC * KK;            // (B,NC)
    float* maps   = scores + (size_t)BN * NCLS;            // (B,K,HW)
    float* attn   = maps + (size_t)BN * KK * HW;           // (B,K)

    k_asq<<<KK, 128>>>(wl);
    k_ab<<<dim3(NCH, BN, 2), 196>>>(x, wl);
    k_softmax<<<dim3(BN, 4), 196>>>(maps);
    k_feat<<<dim3(CC / 32, BN), 256>>>(x, maps, mod, feat);
    k_attn<<<dim3(BN, KK), 256>>>(maps, attn);
    k_scores<<<dim3(NCLS, BN / 4), 128>>>(wcls, scores);
}

// round 7
// speedup vs baseline: 3.7421x; 1.0712x over previous
#include <cuda_runtime.h>
#include <math.h>
#include <stdint.h>

// Problem constants
#define BN   32
#define CC   3072
#define KK   11
#define HW   784
#define NCLS 200
#define NCH  12           // c-chunks for k_ab
#define CCH  (CC / NCH)   // 256 channels per chunk

typedef unsigned long long ull;

// Scratch (device globals; no allocation allowed)
__device__ float g_ab_part[NCH * BN * KK * HW];   // 13.2 MB partial ab
__device__ float g_asq[KK];
__device__ float g_g[BN * CC];                    // sum_k feat_mod

// ---------------------------------------------------------------------------
// f32x2 + cp.async helpers
// ---------------------------------------------------------------------------
__device__ __forceinline__ void ffma2(ull& d, ull a, ull b) {
    asm("fma.rn.f32x2 %0, %1, %2, %0;" : "+l"(d) : "l"(a), "l"(b));
}
__device__ __forceinline__ ull pack2(float lo, float hi) {
    ull r; asm("mov.b64 %0, {%1, %2};" : "=l"(r) : "f"(lo), "f"(hi)); return r;
}
__device__ __forceinline__ float2 unpack2(ull v) {
    float2 r; asm("mov.b64 {%0, %1}, %2;" : "=f"(r.x), "=f"(r.y) : "l"(v)); return r;
}
__device__ __forceinline__ void cp16(uint32_t smem_dst, const void* gsrc) {
    asm volatile("cp.async.cg.shared.global [%0], [%1], 16;"
                 :: "r"(smem_dst), "l"(gsrc));
}
__device__ __forceinline__ void cp_commit() {
    asm volatile("cp.async.commit_group;");
}
template <int N>
__device__ __forceinline__ void cp_wait() {
    asm volatile("cp.async.wait_group %0;" :: "n"(N));
}
__device__ __forceinline__ uint32_t sptr(const void* p) {
    return (uint32_t)__cvta_generic_to_shared(p);
}

// ---------------------------------------------------------------------------
// Kernel 0: a_sq[k] = sum_c w_land[k,c]^2
// ---------------------------------------------------------------------------
__global__ void k_asq(const float* __restrict__ wl) {
    int k = blockIdx.x;
    int tid = threadIdx.x;
    float s = 0.f;
    for (int c = tid; c < CC; c += 128) {
        float w = wl[k * CC + c];
        s += w * w;
    }
    __shared__ float red[128];
    red[tid] = s;
    __syncthreads();
    for (int o = 64; o; o >>= 1) {
        if (tid < o) red[tid] += red[tid + o];
        __syncthreads();
    }
    if (tid == 0) g_asq[k] = red[0];
}

// ---------------------------------------------------------------------------
// Kernel 1: partial ab over a 256-channel chunk, half the pixels per block.
// grid (NCH, BN, 2), block 196. Thread owns one float2 pixel pair.
// x staged through smem via double-buffered cp.async (16 ch x 392 px = 25 KB
// per stage, 16 stages) -> guaranteed deep MLP.
// Dynamic smem: ws2 22528 B + 2 x 25088 B = 72704 B.
// ---------------------------------------------------------------------------
#define AB_STAGES 16
#define AB_SCH    16              // channels per stage
__global__ void __launch_bounds__(196, 3) k_ab(const float* __restrict__ x,
                                               const float* __restrict__ wl) {
    extern __shared__ char smem_ab[];
    ull* ws2 = (ull*)smem_ab;                       // [KK*CCH] 22528 B
    ull* xs[2] = { (ull*)(smem_ab + 22528),         // [16*196] 25088 B each
                   (ull*)(smem_ab + 22528 + 25088) };

    const int ch = blockIdx.x;
    const int b  = blockIdx.y;
    const int ph = blockIdx.z;             // pixel half 0/1
    const int c0 = ch * CCH;
    const int tid = threadIdx.x;

    const float4* x4 = (const float4*)x;

    // kick stage 0, 1 : stage s covers channels [cs*16, cs*16+16)
    // chunk ci in [0,1568): sch = ci/98, p4 = ci%98 ; 8 chunks per thread
#define AB_KICK(s) {                                                          \
        const int buf_ = (s) & 1;                                             \
        uint32_t dbase_ = sptr(xs[buf_]);                                     \
        _Pragma("unroll")                                                     \
        for (int r = 0; r < 8; ++r) {                                         \
            int ci = r * 196 + tid;                                           \
            int sch = ci / 98, p4 = ci - sch * 98;                            \
            const float4* src = x4 +                                          \
                ((size_t)(b * CC + c0 + (s) * AB_SCH + sch) * 196             \
                 + ph * 98 + p4);                                             \
            cp16(dbase_ + sch * 1568 + p4 * 16, src);                         \
        }                                                                     \
        cp_commit();                                                          \
    }

    AB_KICK(0);

    // load weights (duplicated pairs) while stage 0 is in flight
    for (int i = tid; i < KK * CCH; i += 196) {
        int k = i >> 8, c = i & (CCH - 1);
        float w = wl[k * CC + c0 + c];
        ws2[i] = pack2(w, w);
    }

    AB_KICK(1);

    ull acc[KK];
#pragma unroll
    for (int k = 0; k < KK; ++k) acc[k] = 0ull;

    __syncthreads();   // ws2 visible

#pragma unroll 1
    for (int s = 0; s < AB_STAGES; ++s) {
        if (s < AB_STAGES - 1) cp_wait<1>(); else cp_wait<0>();
        __syncthreads();                       // stage s data visible to all

        const ull* xsb = xs[s & 1];
        const int wbase = s * AB_SCH;
#pragma unroll
        for (int c4 = 0; c4 < AB_SCH; c4 += 4) {
            ull xa = xsb[(c4 + 0) * 196 + tid];
            ull xb_ = xsb[(c4 + 1) * 196 + tid];
            ull xc = xsb[(c4 + 2) * 196 + tid];
            ull xd = xsb[(c4 + 3) * 196 + tid];
#pragma unroll
            for (int k = 0; k < KK; ++k) {
                const ulonglong2* wp =
                    (const ulonglong2*)&ws2[k * CCH + wbase + c4];
                ulonglong2 w01 = wp[0];
                ulonglong2 w23 = wp[1];
                ffma2(acc[k], xa, w01.x); ffma2(acc[k], xb_, w01.y);
                ffma2(acc[k], xc, w23.x); ffma2(acc[k], xd, w23.y);
            }
        }

        __syncthreads();                       // everyone done with buf s&1
        if (s + 2 < AB_STAGES) AB_KICK(s + 2); // safe to overwrite now
    }

    ull* gp = reinterpret_cast<ull*>(g_ab_part);
    size_t base = ((size_t)(ch * BN + b) * KK) * HW;
    int po = ph * 196 + tid;
#pragma unroll
    for (int k = 0; k < KK; ++k)
        gp[(base + (size_t)k * HW) / 2 + po] = acc[k];
#undef AB_KICK
}

// ---------------------------------------------------------------------------
// Kernel 2: combine chunks, softmax over K (b_sq cancels), write maps.
// grid (BN, 4 pixel slices), block 196 (1 pixel per thread)
// ---------------------------------------------------------------------------
__global__ void k_softmax(float* __restrict__ maps) {
    const int b = blockIdx.x;
    const int p = blockIdx.y * 196 + threadIdx.x;

    __shared__ float asq[KK];
    if (threadIdx.x < KK) asq[threadIdx.x] = g_asq[threadIdx.x];
    __syncthreads();

    float s[KK];
#pragma unroll
    for (int k = 0; k < KK; ++k) s[k] = 0.f;

#pragma unroll
    for (int ch = 0; ch < NCH; ++ch) {
        size_t base = ((size_t)(ch * BN + b) * KK) * HW + p;
#pragma unroll
        for (int k = 0; k < KK; ++k)
            s[k] += g_ab_part[base + (size_t)k * HW];
    }
    float mx = -1e30f;
#pragma unroll
    for (int k = 0; k < KK; ++k) {
        s[k] = 2.f * s[k] - asq[k];
        mx = fmaxf(mx, s[k]);
    }
    float sum = 0.f;
#pragma unroll
    for (int k = 0; k < KK; ++k) {
        s[k] = __expf(s[k] - mx);
        sum += s[k];
    }
    float inv = 1.f / sum;
#pragma unroll
    for (int k = 0; k < KK; ++k)
        maps[((size_t)(b * KK + k)) * HW + p] = s[k] * inv;
}

// ---------------------------------------------------------------------------
// Kernel 3: feat[b,c,k] = (1/784) * sum_p maps[b,k,p] * x[b,c,p] * mod,
// plus g[b,c] = sum_k feat_mod.
// grid (96, 32), block 256 (8 warps x 4 channels). x staged through smem
// via double-buffered cp.async (32 ch x 196 px = 25 KB/stage, 4 stages).
// Dynamic smem: maps 34496 B + 2 x 25088 B = 84672 B -> 2 blocks/SM.
// ---------------------------------------------------------------------------
#define FT_STAGES 4
__global__ void __launch_bounds__(256, 2) k_feat(const float* __restrict__ x,
                                                 const float* __restrict__ maps,
                                                 const float* __restrict__ mod,
                                                 float* __restrict__ feat) {
    extern __shared__ char smem_ft[];
    ull* maps_s = (ull*)smem_ft;                    // [KK*392] 34496 B
    ull* xs[2] = { (ull*)(smem_ft + 34496),
                   (ull*)(smem_ft + 34496 + 25088) };

    const int b   = (BN - 1) - blockIdx.y;
    const int tid = threadIdx.x;
    const int warp = tid >> 5, lane = tid & 31;
    const int c0 = blockIdx.x * 32;

    const float4* x4 = (const float4*)x;

    // stage s covers pixels [s*196, s*196+196); 32 channels.
    // chunk ci in [0,1568): sch = ci/49, p4 = ci%49
#define FT_KICK(s) {                                                          \
        const int buf_ = (s) & 1;                                             \
        uint32_t dbase_ = sptr(xs[buf_]);                                     \
        for (int ci = tid; ci < 1568; ci += 256) {                            \
            int sch = ci / 49, p4 = ci - sch * 49;                            \
            const float4* src = x4 +                                          \
                ((size_t)(b * CC + c0 + sch) * 196 + (s) * 49 + p4);          \
            cp16(dbase_ + sch * 784 + p4 * 16, src);                          \
        }                                                                     \
        cp_commit();                                                          \
    }

    FT_KICK(0);

    // load maps into smem while stage 0 flies
    const ull* mg = reinterpret_cast<const ull*>(maps + (size_t)b * KK * HW);
    for (int i = tid; i < KK * 392; i += 256) maps_s[i] = mg[i];

    FT_KICK(1);

    ull acc[4][KK];
#pragma unroll
    for (int j = 0; j < 4; ++j)
#pragma unroll
        for (int k = 0; k < KK; ++k) acc[j][k] = 0ull;

    __syncthreads();   // maps_s visible

#pragma unroll 1
    for (int s = 0; s < FT_STAGES; ++s) {
        if (s < FT_STAGES - 1) cp_wait<1>(); else cp_wait<0>();
        __syncthreads();

        const ull* xsb = xs[s & 1];
        const int pbase = s * 98;
#pragma unroll
        for (int i = 0; i < 3; ++i) {
            int pp = lane + i * 32;
            ull x0 = xsb[(4 * warp + 0) * 98 + pp];
            ull x1 = xsb[(4 * warp + 1) * 98 + pp];
            ull x2 = xsb[(4 * warp + 2) * 98 + pp];
            ull x3 = xsb[(4 * warp + 3) * 98 + pp];
#pragma unroll
            for (int k = 0; k < KK; ++k) {
                ull m = maps_s[k * 392 + pbase + pp];
                ffma2(acc[0][k], x0, m);
                ffma2(acc[1][k], x1, m);
                ffma2(acc[2][k], x2, m);
                ffma2(acc[3][k], x3, m);
            }
        }
        if (lane < 2) {                        // tail pairs 96, 97
            int pp = 96 + lane;
            ull x0 = xsb[(4 * warp + 0) * 98 + pp];
            ull x1 = xsb[(4 * warp + 1) * 98 + pp];
            ull x2 = xsb[(4 * warp + 2) * 98 + pp];
            ull x3 = xsb[(4 * warp + 3) * 98 + pp];
#pragma unroll
            for (int k = 0; k < KK; ++k) {
                ull m = maps_s[k * 392 + pbase + pp];
                ffma2(acc[0][k], x0, m);
                ffma2(acc[1][k], x1, m);
                ffma2(acc[2][k], x2, m);
                ffma2(acc[3][k], x3, m);
            }
        }

        __syncthreads();
        if (s + 2 < FT_STAGES) FT_KICK(s + 2);
    }

    const float inv_hw = 1.f / (float)HW;
    const int cg = c0 + warp * 4;
#pragma unroll
    for (int j = 0; j < 4; ++j) {
        float gs = 0.f;
#pragma unroll
        for (int k = 0; k < KK; ++k) {
            float2 v = unpack2(acc[j][k]);
            float s = v.x + v.y;
#pragma unroll
            for (int o = 16; o; o >>= 1)
                s += __shfl_down_sync(0xffffffffu, s, o);
            if (lane == 0) {
                float r = s * inv_hw * mod[(cg + j) * KK + k];
                feat[((size_t)b * CC + cg + j) * KK + k] = r;
                gs += r;
            }
        }
        if (lane == 0) g_g[b * CC + cg + j] = gs;
    }
#undef FT_KICK
}

// ---------------------------------------------------------------------------
// Kernel 4: attn[b,k] = sum_p maps[b,k,p].  grid (BN, KK), block 256
// ---------------------------------------------------------------------------
__global__ void k_attn(const float* __restrict__ maps, float* __restrict__ attn) {
    const int b = blockIdx.x, k = blockIdx.y, tid = threadIdx.x;
    float s = 0.f;
    const float* mp = maps + ((size_t)b * KK + k) * HW;
    for (int i = tid; i < HW; i += 256) s += mp[i];
    __shared__ float red[256];
    red[tid] = s;
    __syncthreads();
    for (int o = 128; o; o >>= 1) {
        if (tid < o) red[tid] += red[tid + o];
        __syncthreads();
    }
    if (tid == 0) attn[b * KK + k] = red[0];
}

// ---------------------------------------------------------------------------
// Kernel 5: scores[b,n] = sum_c g[b,c] * w_cls[n,c]; 4 batches per block.
// grid (NCLS, BN/4), block 128
// ---------------------------------------------------------------------------
__global__ void k_scores(const float* __restrict__ wcls,
                         float* __restrict__ scores) {
    const int n = blockIdx.x;
    const int b0 = blockIdx.y * 4;
    const int tid = threadIdx.x;
    float s0 = 0.f, s1 = 0.f, s2 = 0.f, s3 = 0.f;
    const float* wn = wcls + (size_t)n * CC;
    for (int c = tid; c < CC; c += 128) {
        float w = wn[c];
        s0 = fmaf(w, g_g[(b0 + 0) * CC + c], s0);
        s1 = fmaf(w, g_g[(b0 + 1) * CC + c], s1);
        s2 = fmaf(w, g_g[(b0 + 2) * CC + c], s2);
        s3 = fmaf(w, g_g[(b0 + 3) * CC + c], s3);
    }
    __shared__ float red[4][128];
    red[0][tid] = s0; red[1][tid] = s1; red[2][tid] = s2; red[3][tid] = s3;
    __syncthreads();
    for (int o = 64; o; o >>= 1) {
        if (tid < o) {
            red[0][tid] += red[0][tid + o];
            red[1][tid] += red[1][tid + o];
            red[2][tid] += red[2][tid + o];
            red[3][tid] += red[3][tid + o];
        }
        __syncthreads();
    }
    if (tid == 0) {
#pragma unroll
        for (int j = 0; j < 4; ++j)
            scores[(b0 + j) * NCLS + n] = red[j][0];
    }
}

// ---------------------------------------------------------------------------
extern "C" void kernel_launch(void* const* d_in, const int* in_sizes, int n_in,
                              void* d_out, int out_size) {
    const float* x    = (const float*)d_in[0];
    const float* wl   = (const float*)d_in[1];
    const float* mod  = (const float*)d_in[2];
    const float* wcls = (const float*)d_in[3];

    float* out    = (float*)d_out;
    float* feat   = out;                                   // (B,C,K)
    float* scores = out + (size_t)BN * CC * KK;            // (B,NC)
    float* maps   = scores + (size_t)BN * NCLS;            // (B,K,HW)
    float* attn   = maps + (size_t)BN * KK * HW;           // (B,K)

    // opt-in to >48KB dynamic smem (idempotent)
    cudaFuncSetAttribute(k_ab,   cudaFuncAttributeMaxDynamicSharedMemorySize, 72704);
    cudaFuncSetAttribute(k_feat, cudaFuncAttributeMaxDynamicSharedMemorySize, 84672);

    k_asq<<<KK, 128>>>(wl);
    k_ab<<<dim3(NCH, BN, 2), 196, 72704>>>(x, wl);
    k_softmax<<<dim3(BN, 4), 196>>>(maps);
    k_feat<<<dim3(CC / 32, BN), 256, 84672>>>(x, maps, mod, feat);
    k_attn<<<dim3(BN, KK), 256>>>(maps, attn);
    k_scores<<<dim3(NCLS, BN / 4), 128>>>(wcls, scores);
}